// round 15
// baseline (speedup 1.0000x reference)
#include <cuda_runtime.h>
#include <cstdint>

#define BATCH 8192
#define TMAX  (BATCH * 63)
typedef unsigned long long ull;

__device__ int      g_off[BATCH + 1];
__device__ unsigned g_Pi[BATCH * 384];            // ordered-uint per-(seg,col) max
__device__ __align__(16) int2 g_meta[TMAX];       // per token: {segment id, segment end}

union F2U { ull u; float2 f; };
__device__ __forceinline__ void fma2(ull& a, ull x, ull w) {
    asm("fma.rn.f32x2 %0, %1, %2, %0;" : "+l"(a) : "l"(x), "l"(w));
}
__device__ __forceinline__ unsigned fkey(float f) {
    unsigned b = __float_as_uint(f);
    return (b & 0x80000000u) ? ~b : (b | 0x80000000u);
}
__device__ __forceinline__ float fdec(unsigned k) {
    unsigned b = (k & 0x80000000u) ? (k ^ 0x80000000u) : ~k;
    return __uint_as_float(b);
}
// pack two f32 -> f16x2 (lo = lower-k element)
__device__ __forceinline__ uint32_t pkh(float lo, float hi) {
    uint32_t r;
    asm("cvt.rn.f16x2.f32 %0, %1, %2;" : "=r"(r) : "f"(hi), "f"(lo));
    return r;
}
// m16n8k16 fp16 HMMA, fp32 accumulate (sm_80+ baseline PTX)
__device__ __forceinline__ void mma16(float* d, const uint32_t* a, uint32_t b0, uint32_t b1) {
    asm volatile(
        "mma.sync.aligned.m16n8k16.row.col.f32.f16.f16.f32 "
        "{%0,%1,%2,%3}, {%4,%5,%6,%7}, {%8,%9}, {%0,%1,%2,%3};"
        : "+f"(d[0]), "+f"(d[1]), "+f"(d[2]), "+f"(d[3])
        : "r"(a[0]), "r"(a[1]), "r"(a[2]), "r"(a[3]), "r"(b0), "r"(b1));
}

// ---------------- small setup kernels ----------------
__global__ void k_init() {
    int i = blockIdx.x * blockDim.x + threadIdx.x;
    if (i < BATCH * 384) g_Pi[i] = 0u;
}
__global__ void k_scan(const int* __restrict__ sizes) {
    __shared__ int part[1024];
    int tid = threadIdx.x;
    int base = tid * 8;
    int pref[8];
    int s = 0;
#pragma unroll
    for (int r = 0; r < 8; r++) { pref[r] = s; s += sizes[base + r]; }
    part[tid] = s;
    __syncthreads();
    for (int off = 1; off < 1024; off <<= 1) {
        int v = (tid >= off) ? part[tid - off] : 0;
        __syncthreads();
        part[tid] += v;
        __syncthreads();
    }
    int excl = (tid > 0) ? part[tid - 1] : 0;
#pragma unroll
    for (int r = 0; r < 8; r++) g_off[base + r] = excl + pref[r];
    if (tid == 1023) g_off[BATCH] = part[1023];
}
__global__ void k_prep() {
    int s = blockIdx.x * blockDim.x + threadIdx.x;
    if (s >= BATCH) return;
    int a = g_off[s], e = g_off[s + 1];
    int2 v = make_int2(s, e);
    for (int r = a; r < e; r++) g_meta[r] = v;
}

// ---------------- fp16 HMMA conv, warp-specialized overlap ----------------
// Dense stream, tap shift folded into the GEMM (A-frag row t+j accumulates
// into the same fp32 D frag). One kernel per W, all 128 output channels,
// 512 threads, persistent grid-stride. X stored as PACKED f16x2 in smem
// (XSH=68 words/row, ==4 mod 32 -> conflict-free LDS.32 A-frags, no in-loop
// cvt). Warp roles: NMMA=2*NSLOT mma warps (MF=2, NF=8) never stage; the
// remaining warps LDG-prefetch tile k+1 into registers, cvt f32->f16x2, STS
// into the alternate X buffer CONCURRENTLY with MMA(k). Then transpose D
// into dbuf [tok][132] and all-warp segmented max + ordered-uint atomicMax
// (pre-bias/pre-relu: monotonic). Meta double-buffered alongside X.
template<int W, int TILE, int NSLOT>
__global__ void __launch_bounds__(512, 1) k_hmma(
    const float* __restrict__ x, const float* __restrict__ w, int colbase)
{
    constexpr int XROWS = TILE + 2;
    constexpr int XSH   = 68;              // f16x2 words per X row
    constexpr int WXS   = 68;              // f16x2 words per weight row
    constexpr int NMMA  = NSLOT * 2;
    constexpr int NSTGT = (16 - NMMA) * 32;
    constexpr int NPF   = (XROWS * 32 + NSTGT - 1) / NSTGT;
    constexpr int WW    = W * 128 * WXS;
    constexpr int XW    = XROWS * XSH;
    constexpr int DBW   = TILE * 132;
    constexpr int L     = TILE / 4;

    extern __shared__ uint32_t sm[];
    uint32_t* wsh = sm;                          // [W][128][WXS] f16x2
    uint32_t* xbuf0 = sm + WW;
    uint32_t* xbuf1 = sm + WW + XW;
    float*    db    = (float*)(sm + WW + 2 * XW);            // [TILE][132]
    int2*     mbuf0 = (int2*)(sm + WW + 2 * XW + DBW);       // [TILE]
    int2*     mbuf1 = mbuf0 + TILE;

    const int tid  = threadIdx.x;
    const int lane = tid & 31;
    const int wid  = tid >> 5;
    const int r4   = lane >> 2;
    const int c4l  = lane & 3;
    const bool mma_w = (wid < NMMA);
    const int slot = wid % NSLOT;
    const int cg   = wid / NSLOT;
    const int rb   = slot * 32;
    const int cb   = cg * 64;
    const int stgt = tid - NMMA * 32;      // staging thread id (valid if !mma_w)

    const int Ttot   = g_off[BATCH];
    const int ntiles = (Ttot + TILE - 1) / TILE;

    // stage weights once: global [m][c][j] f32 -> wsh[j][n][kw] f16x2
    for (int idx = tid; idx < W * 128 * 64; idx += 512) {
        int j = idx / (128 * 64);
        int r = idx - j * (128 * 64);
        int n = r >> 6, kw = r & 63;
        float f0 = w[((size_t)n * 128 + 2 * kw)     * W + j];
        float f1 = w[((size_t)n * 128 + 2 * kw + 1) * W + j];
        wsh[j * (128 * WXS) + n * WXS + kw] = pkh(f0, f1);
    }

    // prime buffer 0 with the first tile (all threads)
    {
        int base = blockIdx.x * TILE;
        for (int i = tid; i < XROWS * 32; i += 512) {
            int row = i >> 5, c4 = i & 31;
            int grow = base + row;
            float4 v = make_float4(0.f, 0.f, 0.f, 0.f);
            if (grow < Ttot) v = ((const float4*)x)[(size_t)grow * 128 / 4 + c4];
            xbuf0[row * XSH + 2 * c4]     = pkh(v.x, v.y);
            xbuf0[row * XSH + 2 * c4 + 1] = pkh(v.z, v.w);
        }
        if (tid < TILE)
            mbuf0[tid] = (base + tid < Ttot) ? g_meta[base + tid] : make_int2(0, -1);
    }
    __syncthreads();

    int cur = 0;
    for (int tile = blockIdx.x; tile < ntiles; tile += gridDim.x) {
        const int base = tile * TILE;
        const uint32_t* xp = cur ? xbuf1 : xbuf0;
        const int2* meta_s = cur ? mbuf1 : mbuf0;

        float D[2][8][4];
        if (mma_w) {
            // -------- MMA over xbuf[cur] --------
#pragma unroll
            for (int mf = 0; mf < 2; mf++)
#pragma unroll
                for (int nf = 0; nf < 8; nf++)
#pragma unroll
                    for (int q = 0; q < 4; q++) D[mf][nf][q] = 0.f;
#pragma unroll 2
            for (int kb2 = 0; kb2 < 64; kb2 += 8) {     // f16x2 words per k16
                uint32_t A[2][W][4];
#pragma unroll
                for (int mf = 0; mf < 2; mf++)
#pragma unroll
                    for (int j = 0; j < W; j++) {
                        const uint32_t* p = xp + (rb + mf * 16 + j + r4) * XSH + kb2 + c4l;
                        A[mf][j][0] = p[0];
                        A[mf][j][1] = p[8 * XSH];
                        A[mf][j][2] = p[4];
                        A[mf][j][3] = p[8 * XSH + 4];
                    }
#pragma unroll
                for (int j = 0; j < W; j++)
#pragma unroll
                    for (int nf = 0; nf < 8; nf++) {
                        const uint32_t* q = wsh + j * (128 * WXS)
                                          + (cb + nf * 8 + r4) * WXS + kb2 + c4l;
                        uint32_t b0 = q[0], b1 = q[4];
                        mma16(D[0][nf], A[0][j], b0, b1);
                        mma16(D[1][nf], A[1][j], b0, b1);
                    }
            }
        } else {
            // -------- stage tile k+grid into xbuf[cur^1] (concurrent with MMA) --------
            int nt = tile + gridDim.x;
            int nbase = nt * TILE;
            bool tv = (nt < ntiles);
            uint32_t* xn = cur ? xbuf0 : xbuf1;
            int2* mn = cur ? mbuf0 : mbuf1;
            float4 pf[NPF];
#pragma unroll
            for (int j = 0; j < NPF; j++) {
                int idx = stgt + j * NSTGT;
                int row = idx >> 5, c4 = idx & 31;
                int grow = nbase + row;
                pf[j] = make_float4(0.f, 0.f, 0.f, 0.f);
                if (tv && idx < XROWS * 32 && grow < Ttot)
                    pf[j] = ((const float4*)x)[(size_t)grow * 32 + c4];
            }
            int2 mreg = make_int2(0, -1);
            if (stgt < TILE && tv && nbase + stgt < Ttot) mreg = g_meta[nbase + stgt];
#pragma unroll
            for (int j = 0; j < NPF; j++) {
                int idx = stgt + j * NSTGT;
                if (idx < XROWS * 32) {
                    int row = idx >> 5, c4 = idx & 31;
                    xn[row * XSH + 2 * c4]     = pkh(pf[j].x, pf[j].y);
                    xn[row * XSH + 2 * c4 + 1] = pkh(pf[j].z, pf[j].w);
                }
            }
            if (stgt < TILE) mn[stgt] = mreg;
        }
        __syncthreads();

        // -------- transpose D -> dbuf [tok][132] --------
        if (mma_w) {
#pragma unroll
            for (int mf = 0; mf < 2; mf++)
#pragma unroll
                for (int nf = 0; nf < 8; nf++) {
                    int tok = rb + mf * 16 + r4;
                    int ch  = cb + nf * 8 + 2 * c4l;
                    *(float2*)&db[tok * 132 + ch]       = make_float2(D[mf][nf][0], D[mf][nf][1]);
                    *(float2*)&db[(tok + 8) * 132 + ch] = make_float2(D[mf][nf][2], D[mf][nf][3]);
                }
        }
        __syncthreads();

        // -------- segmented max per channel column (all warps) --------
        {
            const int ch = tid & 127;
            const int t0 = (tid >> 7) * L;
            int   cur_seg = meta_s[t0].x;
            float cm = -3.0e38f;
#pragma unroll 4
            for (int t = t0; t < t0 + L; t++) {
                int2 md = meta_s[t];
                if (md.x != cur_seg) {
                    if (cm > -3.0e38f)
                        atomicMax(&g_Pi[(size_t)cur_seg * 384 + colbase + ch], fkey(cm));
                    cur_seg = md.x; cm = -3.0e38f;
                }
                if (base + t + (W - 1) < md.y) cm = fmaxf(cm, db[t * 132 + ch]);
            }
            if (cm > -3.0e38f)
                atomicMax(&g_Pi[(size_t)cur_seg * 384 + colbase + ch], fkey(cm));
        }
        cur ^= 1;
        __syncthreads();   // epilogue reads done; buffers safe for next phase
    }
}

// ---------------- linear + tanh (decodes pooled maxes, applies bias+relu) ----
__global__ void __launch_bounds__(256, 4) k_lin(
    const float* __restrict__ lw, const float* __restrict__ lb,
    const float* __restrict__ b0, const float* __restrict__ b1,
    const float* __restrict__ b2, float* __restrict__ out)
{
    extern __shared__ float psT[];   // [384][36]
    int tid = threadIdx.x;
    int i0  = blockIdx.x * 32;

    for (int idx = tid; idx < 32 * 384; idx += 256) {
        int i = idx / 384, k = idx - i * 384;
        float bias = (k < 128) ? b0[k] : (k < 256) ? b1[k - 128] : b2[k - 256];
        float f = fdec(g_Pi[(size_t)(i0 + i) * 384 + k]);
        psT[k * 36 + i] = fmaxf(f + bias, 0.f);
    }
    __syncthreads();

    int n  = tid & 63;
    int tg = tid >> 6;
    ull acc[2][4];
#pragma unroll
    for (int h = 0; h < 2; h++)
#pragma unroll
        for (int p = 0; p < 4; p++) acc[h][p] = 0ull;

    const float4* lwa = (const float4*)(lw + (size_t)n * 384);
    const float4* lwb = (const float4*)(lw + (size_t)(n + 64) * 384);
    const float* pbase = psT + tg * 8;

#pragma unroll 2
    for (int k4 = 0; k4 < 96; k4++) {
        float4 wa = __ldg(lwa + k4);
        float4 wb = __ldg(lwb + k4);
        float was[4] = {wa.x, wa.y, wa.z, wa.w};
        float wbs[4] = {wb.x, wb.y, wb.z, wb.w};
#pragma unroll
        for (int q = 0; q < 4; q++) {
            int k = k4 * 4 + q;
            const ulonglong2* pr = (const ulonglong2*)(pbase + k * 36);
            ulonglong2 p01 = pr[0];
            ulonglong2 p23 = pr[1];
            ull wpa, wpb;
            asm("mov.b64 %0, {%1, %1};" : "=l"(wpa) : "f"(was[q]));
            asm("mov.b64 %0, {%1, %1};" : "=l"(wpb) : "f"(wbs[q]));
            fma2(acc[0][0], p01.x, wpa); fma2(acc[1][0], p01.x, wpb);
            fma2(acc[0][1], p01.y, wpa); fma2(acc[1][1], p01.y, wpb);
            fma2(acc[0][2], p23.x, wpa); fma2(acc[1][2], p23.x, wpb);
            fma2(acc[0][3], p23.y, wpa); fma2(acc[1][3], p23.y, wpb);
        }
    }

    float biasa = lb[n], biasb = lb[n + 64];
#pragma unroll
    for (int p = 0; p < 4; p++) {
        F2U ua, ub; ua.u = acc[0][p]; ub.u = acc[1][p];
        int ra = i0 + tg * 8 + 2 * p;
        out[(size_t)ra       * 128 + n]      = tanhf(ua.f.x + biasa);
        out[(size_t)(ra + 1) * 128 + n]      = tanhf(ua.f.y + biasa);
        out[(size_t)ra       * 128 + n + 64] = tanhf(ub.f.x + biasb);
        out[(size_t)(ra + 1) * 128 + n + 64] = tanhf(ub.f.y + biasb);
    }
}

// ---------------- launch ----------------
extern "C" void kernel_launch(void* const* d_in, const int* in_sizes, int n_in,
                              void* d_out, int out_size) {
    const float* x     = (const float*)d_in[0];
    const int*   sizes = (const int*)  d_in[1];
    const float* w0    = (const float*)d_in[2];
    const float* b0    = (const float*)d_in[3];
    const float* w1    = (const float*)d_in[4];
    const float* b1    = (const float*)d_in[5];
    const float* w2    = (const float*)d_in[6];
    const float* b2    = (const float*)d_in[7];
    const float* lw    = (const float*)d_in[8];
    const float* lb    = (const float*)d_in[9];
    float* out = (float*)d_out;

    // smem (bytes): WW + 2*XW + DBW + 2*TILE*2 words, *4
    const int SM1 = (1 * 128 * 68 + 2 * 130 * 68 + 128 * 132 + 2 * 128 * 2) * 4;  // 175,168
    const int SM2 = (2 * 128 * 68 + 2 * 130 * 68 + 128 * 132 + 2 * 128 * 2) * 4;  // 209,984
    const int SM3 = (3 * 128 * 68 + 2 * 98 * 68 + 96 * 132 + 2 * 96 * 2) * 4;     // 209,984
    const int SML = 384 * 36 * 4;                                                 // 55,296

    cudaFuncSetAttribute((const void*)k_hmma<1, 128, 4>, cudaFuncAttributeMaxDynamicSharedMemorySize, SM1);
    cudaFuncSetAttribute((const void*)k_hmma<2, 128, 4>, cudaFuncAttributeMaxDynamicSharedMemorySize, SM2);
    cudaFuncSetAttribute((const void*)k_hmma<3, 96, 3>,  cudaFuncAttributeMaxDynamicSharedMemorySize, SM3);
    cudaFuncSetAttribute((const void*)k_lin, cudaFuncAttributeMaxDynamicSharedMemorySize, SML);

    k_init<<<(BATCH * 384 + 1023) / 1024, 1024>>>();
    k_scan<<<1, 1024>>>(sizes);
    k_prep<<<BATCH / 256, 256>>>();

    k_hmma<1, 128, 4><<<148, 512, SM1>>>(x, w0, 0);
    k_hmma<2, 128, 4><<<148, 512, SM2>>>(x, w1, 128);
    k_hmma<3, 96, 3> <<<148, 512, SM3>>>(x, w2, 256);

    k_lin<<<BATCH / 32, 256, SML>>>(lw, lb, b0, b1, b2, out);
}